// round 15
// baseline (speedup 1.0000x reference)
#include <cuda_runtime.h>
#include <stdint.h>

// Problem constants
#define NB   8
#define HW   128
#define OC   16
#define NF   27
#define NROWS_TOT 1024        // NB*HW global output rows
#define GRID_CONV 148
#define TBL_ITEMS (NF*256*OC) // 110592

// Unified table: [f][ip][o] int16, 32B rows (R12 layout).
__device__ __align__(16) short g_prod[TBL_ITEMS];   // 216KB
__device__ int g_ctr;                                // ticket barrier (monotonic)

// ---------------------------------------------------------------------------
// Fused kernel: 148 blocks (one per SM, all co-resident).
// Phase 0: build table slice -> grid barrier -> Phase 1: R12 conv body.
// ---------------------------------------------------------------------------
#define SM_T_BYTES  (TBL_ITEMS*2)     // 221184
#define TILE_STRIDE 1170              // 9 rows x 130 cols (max TR = 9)
#define SM_TOTAL    (SM_T_BYTES + 3*TILE_STRIDE + 16)   // 224710

__device__ __forceinline__ int tap_byte(const unsigned char* tb, int f,
                                        bool vT, bool vB)
{
    // f compile-time after unroll: offsets fold to immediates
    int cin = f / 9, dh = (f % 9) / 3, dw = f % 3;
    int v = (int)tb[cin*TILE_STRIDE + dh*130 + dw];
    if (dh == 0) v = vT ? v : 128;    // top image boundary -> pad
    if (dh == 2) v = vB ? v : 128;    // bottom image boundary -> pad
    return v;
}

__global__ __launch_bounds__(1024, 1)
void conv_kernel(const float* __restrict__ x,
                 const float* __restrict__ w,
                 const float* __restrict__ bias,
                 const float* __restrict__ sxp,
                 const float* __restrict__ swp,
                 const int*   __restrict__ lut,
                 float* __restrict__ out)
{
    extern __shared__ char smem[];
    unsigned char* stile = (unsigned char*)(smem + SM_T_BYTES);

    const int tid = threadIdx.x;
    const int bid = blockIdx.x;

    // ---- Phase 0: build this block's slice of the global table ----
    {
        const int lo = (bid * TBL_ITEMS) / GRID_CONV;
        const int hi = ((bid + 1) * TBL_ITEMS) / GRID_CONV;
        for (int idx = lo + tid; idx < hi; idx += 1024) {
            int o  = idx & 15;
            int ip = (idx >> 4) & 255;
            int f  = idx >> 12;
            float q = rintf(w[o*NF + f] / swp[0]);   // round-half-even
            q = fminf(fmaxf(q, -127.0f), 127.0f);
            int iw = (int)q + 128;
            int2 hl = ((const int2*)lut)[ip*256 + iw];   // (hi, lo)
            g_prod[(f*256 + ip)*16 + o] = (short)(hl.x*256 + (hl.y & 255));
        }
    }

    // Balanced contiguous global-row range [s, e)
    const int s  = (bid * NROWS_TOT) / GRID_CONV;
    const int e  = ((bid + 1) * NROWS_TOT) / GRID_CONV;
    const int TR = e - s + 2;                    // tile rows incl. halo (8 or 9)

    // ---- Stage + quantize tile (independent of table; hides barrier skew) ----
    {
        const float sx = sxp[0];
        #pragma unroll 1
        for (int cin = 0; cin < 3; cin++) {
            for (int t = tid; t < TR*130; t += 1024) {
                int rr = t / 130;
                int cc = t - rr*130;
                int g  = s - 1 + rr;             // global row
                int ww = cc - 1;
                unsigned char v = 128;
                if ((unsigned)g < (unsigned)NROWS_TOT && (unsigned)ww < 128u) {
                    int b = g >> 7, h = g & 127;
                    float xf = x[((b*3 + cin)*128 + h)*128 + ww];
                    float q = rintf(xf / sx);    // round-half-even
                    q = fminf(fmaxf(q, -127.0f), 127.0f);
                    v = (unsigned char)((int)q + 128);
                }
                stile[cin*TILE_STRIDE + t] = v;
            }
        }
    }

    // ---- Grid barrier (ticket, monotonic counter -> graph-replay safe) ----
    // All 148 blocks are co-resident (1/SM, grid == SM count), so spinning
    // cannot deadlock. Launch n's arrivals are tickets n*148..n*148+147.
    __syncthreads();                 // block's own table writes issued
    if (tid == 0) {
        __threadfence();             // make g_prod slice visible
        int xt = atomicAdd(&g_ctr, 1);
        int target = (xt / GRID_CONV + 1) * GRID_CONV;
        while (atomicAdd(&g_ctr, 0) < target)
            __nanosleep(64);
    }
    __syncthreads();

    // ---- Stage the 216KB table ----
    {
        const int4* src = (const int4*)g_prod;
        int4* dst = (int4*)smem;
        for (int i = tid; i < SM_T_BYTES/16; i += 1024)
            dst[i] = src[i];
    }
    __syncthreads();

    // ---- Phase 1: R12 conv body (pair-per-pixel, 4-slot circular buffer) ----
    const int   hf = tid & 1;                    // channel half
    const float sc = sxp[0] * swp[0];
    const uint4* T = (const uint4*)smem;         // 2 uint4 per 32B row
    const int   P  = (e - s) * 128;              // pixels in range

    #pragma unroll 1
    for (int pp = tid >> 1; pp < P; pp += 512) {
        const int rl = pp >> 7;
        const int c  = pp & 127;
        const int r  = s + rl;
        const int h  = r & 127;
        const int b  = r >> 7;
        const bool vT = (h != 0);
        const bool vB = (h != 127);
        const unsigned char* tb = &stile[rl*130 + c];

        int acc[8];
        #pragma unroll
        for (int o = 0; o < 8; o++) acc[o] = 0;

        uint4 buf[4];
        #pragma unroll
        for (int j = 0; j < 4; j++) {
            int ip = tap_byte(tb, j, vT, vB);
            buf[j] = T[(j*256 + ip)*2 + hf];
        }

        #pragma unroll
        for (int f = 0; f < 27; f++) {
            uint4 v = buf[f & 3];
            if (f + 4 < 27) {
                int ipn = tap_byte(tb, f + 4, vT, vB);
                buf[f & 3] = T[((f + 4)*256 + ipn)*2 + hf];
            }
            acc[0] = __dp2a_lo((int)v.x, 0x0001, acc[0]);
            acc[1] = __dp2a_lo((int)v.x, 0x0100, acc[1]);
            acc[2] = __dp2a_lo((int)v.y, 0x0001, acc[2]);
            acc[3] = __dp2a_lo((int)v.y, 0x0100, acc[3]);
            acc[4] = __dp2a_lo((int)v.z, 0x0001, acc[4]);
            acc[5] = __dp2a_lo((int)v.z, 0x0100, acc[5]);
            acc[6] = __dp2a_lo((int)v.w, 0x0001, acc[6]);
            acc[7] = __dp2a_lo((int)v.w, 0x0100, acc[7]);
            asm volatile("" ::: "memory");       // bound motion: 4-tap window
        }

        float* ob = &out[((b*OC + hf*8)*128 + h)*128 + c];
        #pragma unroll
        for (int o = 0; o < 8; o++)
            ob[o*128*128] = (float)acc[o] * sc + __ldg(&bias[hf*8 + o]);
    }
}

// ---------------------------------------------------------------------------
extern "C" void kernel_launch(void* const* d_in, const int* in_sizes, int n_in,
                              void* d_out, int out_size)
{
    const float* x    = (const float*)d_in[0];
    const float* w    = (const float*)d_in[1];
    const float* bias = (const float*)d_in[2];
    const float* sx   = (const float*)d_in[3];
    const float* sw   = (const float*)d_in[4];
    const int*   lut  = (const int*)d_in[5];
    float* out = (float*)d_out;

    cudaFuncSetAttribute(conv_kernel,
                         cudaFuncAttributeMaxDynamicSharedMemorySize, SM_TOTAL);

    conv_kernel<<<GRID_CONV, 1024, SM_TOTAL>>>(x, w, bias, sx, sw, lut, out);
}

// round 16
// speedup vs baseline: 1.1235x; 1.1235x over previous
#include <cuda_runtime.h>
#include <stdint.h>

// Problem constants
#define NB   8
#define HW   128
#define OC   16
#define NF   27
#define NROWS_TOT 1024        // NB*HW global output rows
#define GRID_CONV 148

// Unified table: [f][ip][o] int16, 32B rows. Both 16B halves of a row share
// one 128B line -> 2-lane pixel pairing shares gather lines.
__device__ __align__(16) short g_prod[NF*256*OC];   // 216KB

// ---------------------------------------------------------------------------
// Table builder: one thread per (f, ip, o).
// ---------------------------------------------------------------------------
__global__ void prep_table(const float* __restrict__ w,
                           const float* __restrict__ swp,
                           const int*   __restrict__ lut)
{
    int idx = blockIdx.x * blockDim.x + threadIdx.x;   // 110592
    if (idx >= NF*256*OC) return;
    int o  = idx & 15;
    int ip = (idx >> 4) & 255;
    int f  = idx >> 12;

    float q = rintf(w[o*NF + f] / swp[0]);   // round-half-even like jnp.round
    q = fminf(fmaxf(q, -127.0f), 127.0f);
    int iw = (int)q + 128;

    int2 hl = ((const int2*)lut)[ip*256 + iw];   // (hi, lo)
    g_prod[(f*256 + ip)*16 + o] = (short)(hl.x*256 + (hl.y & 255));
}

// ---------------------------------------------------------------------------
// Conv (R12 body): 148 blocks (one per SM), balanced contiguous row ranges.
// Thread pair = pixel (tid&1 selects channel half). 4-slot circular buffer.
// CHANGE vs R12: table staged via cp.async, overlapped with tile staging.
// ---------------------------------------------------------------------------
#define SM_T_BYTES  (NF*256*OC*2)     // 221184
#define T_I4        (SM_T_BYTES/16)   // 13824 int4 units
#define TILE_STRIDE 1170              // 9 rows x 130 cols (max TR = 9)
#define SM_TOTAL    (SM_T_BYTES + 3*TILE_STRIDE + 16)   // 224710

#define CP_ASYNC16(dst_u32, src)                                        \
    asm volatile("cp.async.cg.shared.global [%0], [%1], 16;"            \
                 :: "r"(dst_u32), "l"(src) : "memory")

__device__ __forceinline__ int tap_byte(const unsigned char* tb, int f,
                                        bool vT, bool vB)
{
    // f compile-time after unroll: offsets fold to immediates
    int cin = f / 9, dh = (f % 9) / 3, dw = f % 3;
    int v = (int)tb[cin*TILE_STRIDE + dh*130 + dw];
    if (dh == 0) v = vT ? v : 128;    // top image boundary -> pad
    if (dh == 2) v = vB ? v : 128;    // bottom image boundary -> pad
    return v;
}

__global__ __launch_bounds__(1024, 1)
void conv_kernel(const float* __restrict__ x,
                 const float* __restrict__ bias,
                 const float* __restrict__ sxp,
                 const float* __restrict__ swp,
                 float* __restrict__ out)
{
    extern __shared__ char smem[];
    unsigned char* stile = (unsigned char*)(smem + SM_T_BYTES);

    const int tid = threadIdx.x;
    const int bid = blockIdx.x;

    // Balanced contiguous global-row range [s, e)
    const int s  = (bid * NROWS_TOT) / GRID_CONV;
    const int e  = ((bid + 1) * NROWS_TOT) / GRID_CONV;
    const int TR = e - s + 2;                    // tile rows incl. halo (8 or 9)

    // ---- Issue the 216KB table staging asynchronously (fire-and-forget) ----
    {
        const uint32_t sm = (uint32_t)__cvta_generic_to_shared(smem);
        const char* gp = (const char*)g_prod;
        #pragma unroll
        for (int k = 0; k < 13; k++) {
            int i = tid + k*1024;
            CP_ASYNC16(sm + i*16, gp + i*16);
        }
        if (tid < (T_I4 - 13*1024)) {            // 512 remaining
            int i = tid + 13*1024;
            CP_ASYNC16(sm + i*16, gp + i*16);
        }
        asm volatile("cp.async.commit_group;" ::: "memory");
    }

    // ---- Stage + quantize tile [3][TR][130] while the table streams in ----
    {
        const float sx = sxp[0];
        #pragma unroll 1
        for (int cin = 0; cin < 3; cin++) {
            for (int t = tid; t < TR*130; t += 1024) {
                int rr = t / 130;
                int cc = t - rr*130;
                int g  = s - 1 + rr;             // global row
                int ww = cc - 1;
                unsigned char v = 128;
                if ((unsigned)g < (unsigned)NROWS_TOT && (unsigned)ww < 128u) {
                    int b = g >> 7, h = g & 127;
                    float xf = x[((b*3 + cin)*128 + h)*128 + ww];
                    float q = rintf(xf / sx);    // round-half-even
                    q = fminf(fmaxf(q, -127.0f), 127.0f);
                    v = (unsigned char)((int)q + 128);
                }
                stile[cin*TILE_STRIDE + t] = v;
            }
        }
    }

    asm volatile("cp.async.wait_group 0;" ::: "memory");
    __syncthreads();

    // ---- Mainloop: byte-identical to R12 ----
    const int   hf = tid & 1;                    // channel half: 0 -> 0-7, 1 -> 8-15
    const float sc = sxp[0] * swp[0];
    const uint4* T = (const uint4*)smem;         // 2 uint4 per 32B row
    const int   P  = (e - s) * 128;              // pixels in this block's range

    #pragma unroll 1
    for (int pp = tid >> 1; pp < P; pp += 512) {
        const int rl = pp >> 7;                  // local row
        const int c  = pp & 127;                 // column
        const int r  = s + rl;                   // global row
        const int h  = r & 127;
        const int b  = r >> 7;
        const bool vT = (h != 0);                // warp-uniform predicates
        const bool vB = (h != 127);
        const unsigned char* tb = &stile[rl*130 + c];

        int acc[8];
        #pragma unroll
        for (int o = 0; o < 8; o++) acc[o] = 0;

        // Prime 4-deep circular buffer (4 LDS.128 in flight per warp)
        uint4 buf[4];
        #pragma unroll
        for (int j = 0; j < 4; j++) {
            int ip = tap_byte(tb, j, vT, vB);
            buf[j] = T[(j*256 + ip)*2 + hf];
        }

        #pragma unroll
        for (int f = 0; f < 27; f++) {
            uint4 v = buf[f & 3];
            if (f + 4 < 27) {                    // refill slot with tap f+4
                int ipn = tap_byte(tb, f + 4, vT, vB);
                buf[f & 3] = T[((f + 4)*256 + ipn)*2 + hf];
            }
            acc[0] = __dp2a_lo((int)v.x, 0x0001, acc[0]);
            acc[1] = __dp2a_lo((int)v.x, 0x0100, acc[1]);
            acc[2] = __dp2a_lo((int)v.y, 0x0001, acc[2]);
            acc[3] = __dp2a_lo((int)v.y, 0x0100, acc[3]);
            acc[4] = __dp2a_lo((int)v.z, 0x0001, acc[4]);
            acc[5] = __dp2a_lo((int)v.z, 0x0100, acc[5]);
            acc[6] = __dp2a_lo((int)v.w, 0x0001, acc[6]);
            acc[7] = __dp2a_lo((int)v.w, 0x0100, acc[7]);
            asm volatile("" ::: "memory");       // bound motion: 4-tap window
        }

        float* ob = &out[((b*OC + hf*8)*128 + h)*128 + c];
        #pragma unroll
        for (int o = 0; o < 8; o++)
            ob[o*128*128] = (float)acc[o] * sc + __ldg(&bias[hf*8 + o]);
    }
}

// ---------------------------------------------------------------------------
extern "C" void kernel_launch(void* const* d_in, const int* in_sizes, int n_in,
                              void* d_out, int out_size)
{
    const float* x    = (const float*)d_in[0];
    const float* w    = (const float*)d_in[1];
    const float* bias = (const float*)d_in[2];
    const float* sx   = (const float*)d_in[3];
    const float* sw   = (const float*)d_in[4];
    const int*   lut  = (const int*)d_in[5];
    float* out = (float*)d_out;

    cudaFuncSetAttribute(conv_kernel,
                         cudaFuncAttributeMaxDynamicSharedMemorySize, SM_TOTAL);

    prep_table<<<(NF*256*OC + 255) / 256, 256>>>(w, sw, lut);
    conv_kernel<<<GRID_CONV, 1024, SM_TOTAL>>>(x, bias, sx, sw, out);
}

// round 17
// speedup vs baseline: 1.1608x; 1.0332x over previous
#include <cuda_runtime.h>
#include <stdint.h>

// Problem constants
#define NB   8
#define HW   128
#define OC   16
#define NF   27
#define NROWS_TOT 1024        // NB*HW global output rows
#define GRID_CONV 148
#define TBL_ITEMS (NF*256*OC) // 110592 = 432 * 256 exactly

// Unified table: [f][ip][o] int16, 32B rows.
__device__ __align__(16) short g_prod[TBL_ITEMS];   // 216KB

// ---------------------------------------------------------------------------
// Table builder: one thread per (f, ip, o). Grid sized exactly -> no bounds
// check, every CTA reaches the PDL trigger.
// ---------------------------------------------------------------------------
__global__ void prep_table(const float* __restrict__ w,
                           const float* __restrict__ swp,
                           const int*   __restrict__ lut)
{
    int idx = blockIdx.x * blockDim.x + threadIdx.x;   // < 110592 by grid size
    int o  = idx & 15;
    int ip = (idx >> 4) & 255;
    int f  = idx >> 12;

    float q = rintf(w[o*NF + f] / swp[0]);   // round-half-even like jnp.round
    q = fminf(fmaxf(q, -127.0f), 127.0f);
    int iw = (int)q + 128;

    int2 hl = ((const int2*)lut)[ip*256 + iw];   // (hi, lo)
    g_prod[(f*256 + ip)*16 + o] = (short)(hl.x*256 + (hl.y & 255));

    // PDL: signal completion (each thread triggers after its own store;
    // the dependent grid's griddepsync orders all of them).
    cudaTriggerProgrammaticLaunchCompletion();
}

// ---------------------------------------------------------------------------
// Conv (R16 body): 148 blocks, balanced row ranges, pair-per-pixel,
// 4-slot circular buffer. PDL: tile staging runs BEFORE the dependency sync,
// overlapping prep's execution; table cp.async after the sync.
// ---------------------------------------------------------------------------
#define SM_T_BYTES  (TBL_ITEMS*2)     // 221184
#define T_I4        (SM_T_BYTES/16)   // 13824 int4 units
#define TILE_STRIDE 1170              // 9 rows x 130 cols (max TR = 9)
#define SM_TOTAL    (SM_T_BYTES + 3*TILE_STRIDE + 16)   // 224710

#define CP_ASYNC16(dst_u32, src)                                        \
    asm volatile("cp.async.cg.shared.global [%0], [%1], 16;"            \
                 :: "r"(dst_u32), "l"(src) : "memory")

__device__ __forceinline__ int tap_byte(const unsigned char* tb, int f,
                                        bool vT, bool vB)
{
    // f compile-time after unroll: offsets fold to immediates
    int cin = f / 9, dh = (f % 9) / 3, dw = f % 3;
    int v = (int)tb[cin*TILE_STRIDE + dh*130 + dw];
    if (dh == 0) v = vT ? v : 128;    // top image boundary -> pad
    if (dh == 2) v = vB ? v : 128;    // bottom image boundary -> pad
    return v;
}

__global__ __launch_bounds__(1024, 1)
void conv_kernel(const float* __restrict__ x,
                 const float* __restrict__ bias,
                 const float* __restrict__ sxp,
                 const float* __restrict__ swp,
                 float* __restrict__ out)
{
    extern __shared__ char smem[];
    unsigned char* stile = (unsigned char*)(smem + SM_T_BYTES);

    const int tid = threadIdx.x;
    const int bid = blockIdx.x;

    // Balanced contiguous global-row range [s, e)
    const int s  = (bid * NROWS_TOT) / GRID_CONV;
    const int e  = ((bid + 1) * NROWS_TOT) / GRID_CONV;
    const int TR = e - s + 2;                    // tile rows incl. halo (8 or 9)

    // ---- Tile staging FIRST: needs only x, overlaps prep via PDL ----
    {
        const float sx = sxp[0];
        #pragma unroll 1
        for (int cin = 0; cin < 3; cin++) {
            for (int t = tid; t < TR*130; t += 1024) {
                int rr = t / 130;
                int cc = t - rr*130;
                int g  = s - 1 + rr;             // global row
                int ww = cc - 1;
                unsigned char v = 128;
                if ((unsigned)g < (unsigned)NROWS_TOT && (unsigned)ww < 128u) {
                    int b = g >> 7, h = g & 127;
                    float xf = x[((b*3 + cin)*128 + h)*128 + ww];
                    float q = rintf(xf / sx);    // round-half-even
                    q = fminf(fmaxf(q, -127.0f), 127.0f);
                    v = (unsigned char)((int)q + 128);
                }
                stile[cin*TILE_STRIDE + t] = v;
            }
        }
    }

    // ---- Wait for prep's table writes, then stream the table in ----
    cudaGridDependencySynchronize();
    {
        const uint32_t sm = (uint32_t)__cvta_generic_to_shared(smem);
        const char* gp = (const char*)g_prod;
        #pragma unroll
        for (int k = 0; k < 13; k++) {
            int i = tid + k*1024;
            CP_ASYNC16(sm + i*16, gp + i*16);
        }
        if (tid < (T_I4 - 13*1024)) {            // 512 remaining
            int i = tid + 13*1024;
            CP_ASYNC16(sm + i*16, gp + i*16);
        }
        asm volatile("cp.async.commit_group;" ::: "memory");
        asm volatile("cp.async.wait_group 0;" ::: "memory");
    }
    __syncthreads();

    // ---- Mainloop: byte-identical to R16/R12 ----
    const int   hf = tid & 1;                    // channel half: 0 -> 0-7, 1 -> 8-15
    const float sc = sxp[0] * swp[0];
    const uint4* T = (const uint4*)smem;         // 2 uint4 per 32B row
    const int   P  = (e - s) * 128;              // pixels in this block's range

    #pragma unroll 1
    for (int pp = tid >> 1; pp < P; pp += 512) {
        const int rl = pp >> 7;                  // local row
        const int c  = pp & 127;                 // column
        const int r  = s + rl;                   // global row
        const int h  = r & 127;
        const int b  = r >> 7;
        const bool vT = (h != 0);                // warp-uniform predicates
        const bool vB = (h != 127);
        const unsigned char* tb = &stile[rl*130 + c];

        int acc[8];
        #pragma unroll
        for (int o = 0; o < 8; o++) acc[o] = 0;

        // Prime 4-deep circular buffer (4 LDS.128 in flight per warp)
        uint4 buf[4];
        #pragma unroll
        for (int j = 0; j < 4; j++) {
            int ip = tap_byte(tb, j, vT, vB);
            buf[j] = T[(j*256 + ip)*2 + hf];
        }

        #pragma unroll
        for (int f = 0; f < 27; f++) {
            uint4 v = buf[f & 3];
            if (f + 4 < 27) {                    // refill slot with tap f+4
                int ipn = tap_byte(tb, f + 4, vT, vB);
                buf[f & 3] = T[((f + 4)*256 + ipn)*2 + hf];
            }
            acc[0] = __dp2a_lo((int)v.x, 0x0001, acc[0]);
            acc[1] = __dp2a_lo((int)v.x, 0x0100, acc[1]);
            acc[2] = __dp2a_lo((int)v.y, 0x0001, acc[2]);
            acc[3] = __dp2a_lo((int)v.y, 0x0100, acc[3]);
            acc[4] = __dp2a_lo((int)v.z, 0x0001, acc[4]);
            acc[5] = __dp2a_lo((int)v.z, 0x0100, acc[5]);
            acc[6] = __dp2a_lo((int)v.w, 0x0001, acc[6]);
            acc[7] = __dp2a_lo((int)v.w, 0x0100, acc[7]);
            asm volatile("" ::: "memory");       // bound motion: 4-tap window
        }

        float* ob = &out[((b*OC + hf*8)*128 + h)*128 + c];
        #pragma unroll
        for (int o = 0; o < 8; o++)
            ob[o*128*128] = (float)acc[o] * sc + __ldg(&bias[hf*8 + o]);
    }
}

// ---------------------------------------------------------------------------
extern "C" void kernel_launch(void* const* d_in, const int* in_sizes, int n_in,
                              void* d_out, int out_size)
{
    const float* x    = (const float*)d_in[0];
    const float* w    = (const float*)d_in[1];
    const float* bias = (const float*)d_in[2];
    const float* sx   = (const float*)d_in[3];
    const float* sw   = (const float*)d_in[4];
    const int*   lut  = (const int*)d_in[5];
    float* out = (float*)d_out;

    cudaFuncSetAttribute(conv_kernel,
                         cudaFuncAttributeMaxDynamicSharedMemorySize, SM_TOTAL);

    // Primary: table builder (grid exactly covers TBL_ITEMS)
    prep_table<<<TBL_ITEMS / 256, 256>>>(w, sw, lut);

    // Secondary: conv with programmatic dependent launch -> overlaps prep
    cudaLaunchConfig_t cfg = {};
    cfg.gridDim  = dim3(GRID_CONV, 1, 1);
    cfg.blockDim = dim3(1024, 1, 1);
    cfg.dynamicSmemBytes = SM_TOTAL;
    cfg.stream = 0;                               // capture stream (default)
    cudaLaunchAttribute attrs[1];
    attrs[0].id = cudaLaunchAttributeProgrammaticStreamSerialization;
    attrs[0].val.programmaticStreamSerializationAllowed = 1;
    cfg.attrs = attrs;
    cfg.numAttrs = 1;
    cudaLaunchKernelEx(&cfg, conv_kernel, x, bias, sx, sw, out);
}